// round 3
// baseline (speedup 1.0000x reference)
#include <cuda_runtime.h>
#include <cuda_bf16.h>
#include <math.h>
#include <stdint.h>

#define Bb 64
#define LL 196
#define TT 32
#define MAXT 31
#define ED 2048
#define AD 512
#define DD 512
#define VV 10000
#define XK 3072
#define HSPLIT 4
#define GSPLIT 12
#define FCN 10112
#define FCLD 10112

// d_out layout (float32): predictions, caps, dl, alphas, sort_idx
#define PRED_OFF  0
#define CAPS_OFF  (Bb*MAXT*VV)
#define DL_OFF    (CAPS_OFF + Bb*TT)
#define ALPHA_OFF (DL_OFF + Bb)
#define SIDX_OFF  (ALPHA_OFF + Bb*MAXT*LL)

// ------------------- static device scratch -------------------
__device__ int   g_sidx[Bb];
__device__ int   g_nb[MAXT];
__device__ float g_h[Bb*DD];
__device__ float g_c[Bb*DD];
__device__ float g_beta[Bb];
__device__ float g_energy[Bb*LL];
__device__ float g_xcat[Bb*XK];
__device__ float g_WaEnc[(size_t)Bb*LL*AD];
__device__ float g_hUpart[HSPLIT*Bb*AD];
__device__ float g_gatesPart[GSPLIT*Bb*2048];
__device__ float g_fcPart[2*Bb*FCLD];
__device__ float g_initPart[16*Bb*DD];

// packed bf16-split operands: uint2 {hi_pair(k,k+1), lo_pair(k,k+1)}
__device__ uint2 g_encPk[(size_t)Bb*LL*(ED/2)];     // [12544][1024]
__device__ uint2 g_WaT  [(size_t)AD*(ED/2)];        // [512][1024]
__device__ uint2 g_UaT  [(size_t)AD*(DD/2)];        // [512][256]
__device__ uint2 g_WcatPk[(size_t)2048*(XK/2)];     // [2048][1536]
__device__ uint2 g_fcT  [(size_t)FCN*(DD/2)];       // [10112][256]
__device__ uint2 g_ihT  [(size_t)DD*(ED/2)];        // [512][1024]
__device__ uint2 g_icT  [(size_t)DD*(ED/2)];
__device__ uint2 g_meanPk[Bb*(ED/2)];
__device__ uint2 g_xcatPk[Bb*(XK/2)];
__device__ uint2 g_hPk  [Bb*(DD/2)];

__device__ __forceinline__ float sigmoidf_(float x){ return 1.0f/(1.0f+expf(-x)); }
__device__ __forceinline__ float tanh_hw(float x){
    float r; asm("tanh.approx.f32 %0, %1;" : "=f"(r) : "f"(x)); return r;
}
__device__ __forceinline__ uint2 packsplit(float x0, float x1){
    __nv_bfloat16 h0 = __float2bfloat16_rn(x0);
    __nv_bfloat16 h1 = __float2bfloat16_rn(x1);
    __nv_bfloat16 l0 = __float2bfloat16_rn(x0 - __bfloat162float(h0));
    __nv_bfloat16 l1 = __float2bfloat16_rn(x1 - __bfloat162float(h1));
    uint2 u;
    u.x = (uint32_t)__bfloat16_as_ushort(h0) | ((uint32_t)__bfloat16_as_ushort(h1) << 16);
    u.y = (uint32_t)__bfloat16_as_ushort(l0) | ((uint32_t)__bfloat16_as_ushort(l1) << 16);
    return u;
}
__device__ __forceinline__ void mma16816(float* c,
    uint32_t a0, uint32_t a1, uint32_t a2, uint32_t a3, uint32_t b0, uint32_t b1)
{
    asm volatile(
        "mma.sync.aligned.m16n8k16.row.col.f32.bf16.bf16.f32 "
        "{%0,%1,%2,%3},{%4,%5,%6,%7},{%8,%9},{%0,%1,%2,%3};"
        : "+f"(c[0]), "+f"(c[1]), "+f"(c[2]), "+f"(c[3])
        : "r"(a0), "r"(a1), "r"(a2), "r"(a3), "r"(b0), "r"(b1));
}

// ------------------- sort -------------------
__global__ void k_sort(const int* __restrict__ lengths, const int* __restrict__ captions,
                       float* __restrict__ out)
{
    __shared__ int slen[Bb];
    __shared__ int sdl[Bb];
    int i = threadIdx.x;
    slen[i] = lengths[i];
    __syncthreads();
    int li = slen[i];
    int rank = 0;
    #pragma unroll 8
    for (int j = 0; j < Bb; j++) {
        int lj = slen[j];
        if (lj > li || (lj == li && j < i)) rank++;
    }
    g_sidx[rank] = i;
    __syncthreads();
    int src = g_sidx[i];
    int dl  = slen[src] - 1;
    sdl[i] = dl;
    out[DL_OFF + i]   = (float)dl;
    out[SIDX_OFF + i] = (float)src;
    for (int t2 = 0; t2 < TT; t2++)
        out[CAPS_OFF + i*TT + t2] = (float)captions[src*TT + t2];
    __syncthreads();
    if (i < MAXT) {
        int c = 0;
        for (int j = 0; j < Bb; j++) if (sdl[j] > i) c++;
        g_nb[i] = c;
    }
}

// ------------------- conversions -------------------
// enc fp32 [12544][2048] -> packed (no gather; gathered at GEMM)
__global__ void k_cvt_enc(const float* __restrict__ enc)
{
    int row = blockIdx.x;
    const float* r = enc + (size_t)row*ED;
    uint2* o = g_encPk + (size_t)row*(ED/2);
    #pragma unroll
    for (int i = 0; i < 4; i++) {
        int p = threadIdx.x + i*256;
        o[p] = packsplit(r[2*p], r[2*p+1]);
    }
}

// generic W[K][N] fp32 -> out uint2[NP][K/2] (transpose + split); pad rows >= N with 0
__global__ void k_cvt_wT(const float* __restrict__ W, uint2* __restrict__ out,
                         int N, int NP, int Kp)
{
    int kp = blockIdx.x;
    int n = blockIdx.y*256 + threadIdx.x;
    if (n >= NP) return;
    float v0 = 0.f, v1 = 0.f;
    if (n < N) { v0 = W[(size_t)(2*kp)*N + n]; v1 = W[(size_t)(2*kp+1)*N + n]; }
    out[(size_t)n*Kp + kp] = packsplit(v0, v1);
}

// Wcat[n][k] = k<2560 ? W_ih[n][k] : W_hh[n][k-2560]   (already n-major)
__global__ void k_cvt_wcat(const float* __restrict__ W_ih, const float* __restrict__ W_hh)
{
    int n = blockIdx.x;
    uint2* o = g_WcatPk + (size_t)n*(XK/2);
    #pragma unroll
    for (int i = 0; i < 6; i++) {
        int kp = threadIdx.x + i*256;
        int k0 = 2*kp;
        float v0 = (k0   < 2560) ? W_ih[(size_t)n*2560 + k0]   : W_hh[(size_t)n*512 + (k0-2560)];
        float v1 = (k0+1 < 2560) ? W_ih[(size_t)n*2560 + k0+1] : W_hh[(size_t)n*512 + (k0+1-2560)];
        o[kp] = packsplit(v0, v1);
    }
}

// xcat fp32 -> packed
__global__ void k_cvt_xcat(int t)
{
    int b = blockIdx.x;
    if (b >= g_nb[t]) return;
    int p = blockIdx.y*256 + threadIdx.x;   // 0..1535
    g_xcatPk[(size_t)b*(XK/2) + p] = packsplit(g_xcat[(size_t)b*XK + 2*p],
                                               g_xcat[(size_t)b*XK + 2*p+1]);
}

// ------------------- encoder mean (gathered) + pack -------------------
__global__ void k_mean(const float* __restrict__ enc)
{
    int b = blockIdx.x;
    int p = blockIdx.y*256 + threadIdx.x;   // pair 0..1023
    const float* base = enc + (size_t)g_sidx[b]*LL*ED;
    float s0 = 0.f, s1 = 0.f;
    #pragma unroll 4
    for (int l = 0; l < LL; l++) {
        s0 += base[(size_t)l*ED + 2*p];
        s1 += base[(size_t)l*ED + 2*p+1];
    }
    g_meanPk[b*(ED/2) + p] = packsplit(s0*(1.0f/196.0f), s1*(1.0f/196.0f));
}

// ------------------- bf16-split tensor-core GEMM -------------------
// C(partial z) = A[M,K] @ B^T where BT is [N][K] packed. 3 virtual passes:
// Ah*Bh + Ah*Bl + Al*Bh, fp32 accum. Block = 64(m) x 128(n), 8 warps (4m x 2n).
// Kp = K/2 pairs; grid.z = K-split, partial z at C + z*M*ldc.
template<bool GATHER>
__global__ void __launch_bounds__(256) wgemm(
    const uint2* __restrict__ A, const uint2* __restrict__ BT,
    float* __restrict__ C, int M, int Kp, int ldap, int ldbp, int ldc)
{
    int tid = threadIdx.x;
    int wid = tid >> 5, lane = tid & 31;
    int g = lane >> 2, t = lane & 3;
    int m0 = blockIdx.y*64 + (wid & 3)*16;
    int n0 = blockIdx.x*128 + (wid >> 2)*64;

    int kpPer = Kp / gridDim.z;
    int kp0 = blockIdx.z * kpPer, kp1 = kp0 + kpPer;
    C += (size_t)blockIdx.z * (size_t)M * (size_t)ldc;

    int rA = m0 + g, rB = m0 + g + 8;
    if (GATHER) {
        rA = g_sidx[rA / LL]*LL + (rA % LL);
        rB = g_sidx[rB / LL]*LL + (rB % LL);
    }
    const uint2* Arow0 = A + (size_t)rA*ldap + t;
    const uint2* Arow1 = A + (size_t)rB*ldap + t;
    const uint2* Brow[8];
    #pragma unroll
    for (int j = 0; j < 8; j++)
        Brow[j] = BT + (size_t)(n0 + j*8 + g)*ldbp + t;

    float c[8][4];
    #pragma unroll
    for (int j = 0; j < 8; j++)
        #pragma unroll
        for (int q = 0; q < 4; q++) c[j][q] = 0.f;

    for (int kp = kp0; kp < kp1; kp += 8) {
        uint2 A0 = Arow0[kp], A2 = Arow0[kp+4];
        uint2 A1 = Arow1[kp], A3 = Arow1[kp+4];
        #pragma unroll
        for (int j = 0; j < 8; j++) {
            uint2 B0 = Brow[j][kp], B1 = Brow[j][kp+4];
            mma16816(c[j], A0.x, A1.x, A2.x, A3.x, B0.x, B1.x);  // hi*hi
            mma16816(c[j], A0.x, A1.x, A2.x, A3.x, B0.y, B1.y);  // hi*lo
            mma16816(c[j], A0.y, A1.y, A2.y, A3.y, B0.x, B1.x);  // lo*hi
        }
    }

    #pragma unroll
    for (int j = 0; j < 8; j++) {
        int n = n0 + j*8 + 2*t;
        float* cr0 = C + (size_t)(m0 + g)*ldc + n;
        float* cr1 = C + (size_t)(m0 + g + 8)*ldc + n;
        cr0[0] = c[j][0]; cr0[1] = c[j][1];
        cr1[0] = c[j][2]; cr1[1] = c[j][3];
    }
}

// ------------------- h0/c0 reduce + tanh + pack -------------------
__global__ void k_init(const float* __restrict__ ih_b, const float* __restrict__ ic_b)
{
    int b = blockIdx.x;
    int j0 = threadIdx.x*2;               // pairs
    float sh0 = 0.f, sh1 = 0.f, sc0 = 0.f, sc1 = 0.f;
    #pragma unroll
    for (int ks = 0; ks < 8; ks++) {
        const float* ph = g_initPart + ((size_t)ks*Bb + b)*DD;
        const float* pc = g_initPart + ((size_t)(8+ks)*Bb + b)*DD;
        sh0 += ph[j0]; sh1 += ph[j0+1];
        sc0 += pc[j0]; sc1 += pc[j0+1];
    }
    float h0v = tanhf(sh0 + ih_b[j0]), h1v = tanhf(sh1 + ih_b[j0+1]);
    float c0v = tanhf(sc0 + ic_b[j0]), c1v = tanhf(sc1 + ic_b[j0+1]);
    g_h[b*DD + j0] = h0v; g_h[b*DD + j0+1] = h1v;
    g_c[b*DD + j0] = c0v; g_c[b*DD + j0+1] = c1v;
    g_hPk[b*(DD/2) + threadIdx.x] = packsplit(h0v, h1v);
}

// ------------------- energies + prestep (emb/h copy, beta) -------------------
__global__ void k_energy(const int* __restrict__ captions, const float* __restrict__ embT,
                         const float* __restrict__ fb_W, const float* __restrict__ fb_b,
                         const float* __restrict__ w_att, int t)
{
    int b = blockIdx.x;
    if (b >= g_nb[t]) return;
    int yc = blockIdx.y;
    int tid = threadIdx.x;
    __shared__ float sHU[AD];
    __shared__ float sW[AD];
    __shared__ float sB[8];

    for (int a = tid; a < AD; a += 256) {
        float s = 0.f;
        #pragma unroll
        for (int ks = 0; ks < HSPLIT; ks++)
            s += g_hUpart[((size_t)ks*Bb + b)*AD + a];
        sHU[a] = s;
        sW[a]  = w_att[a];
    }

    if (yc == 0) {
        int cap = captions[g_sidx[b]*TT + t];
        if (tid < 128)
            ((float4*)(g_xcat + (size_t)b*XK))[tid] =
                ((const float4*)(embT + (size_t)cap*DD))[tid];
        else
            ((float4*)(g_xcat + (size_t)b*XK + 2560))[tid-128] =
                ((const float4*)(g_h + (size_t)b*DD))[tid-128];
        float s = g_h[b*DD + tid]       * fb_W[tid]
                + g_h[b*DD + 256 + tid] * fb_W[256 + tid];
        #pragma unroll
        for (int o = 16; o > 0; o >>= 1) s += __shfl_xor_sync(0xffffffffu, s, o);
        if ((tid & 31) == 0) sB[tid >> 5] = s;
    }
    __syncthreads();
    if (yc == 0 && tid == 0) {
        float tot = 0.f;
        #pragma unroll
        for (int w = 0; w < 8; w++) tot += sB[w];
        g_beta[b] = 1.0f / (1.0f + expf(-(tot + fb_b[0])));
    }

    int warp = tid >> 5, lane = tid & 31;
    int lend = min(yc*49 + 49, LL);
    for (int li = yc*49 + warp; li < lend; li += 8) {
        const float* wa = g_WaEnc + ((size_t)b*LL + li)*AD;
        float acc = 0.f;
        for (int a = lane; a < AD; a += 32)
            acc += tanh_hw(wa[a] + sHU[a]) * sW[a];
        #pragma unroll
        for (int o = 16; o > 0; o >>= 1) acc += __shfl_xor_sync(0xffffffffu, acc, o);
        if (lane == 0) g_energy[b*LL + li] = acc;
    }
}

// ------------------- softmax + context + alpha out -------------------
__global__ void k_context(const float* __restrict__ enc, float* __restrict__ out, int t)
{
    int b = blockIdx.x;
    if (b >= g_nb[t]) return;
    int ec = blockIdx.y;
    int tid = threadIdx.x;
    __shared__ float sAl[LL];
    __shared__ float sred[8];

    float v = (tid < LL) ? g_energy[b*LL + tid] : -3.4e38f;
    float m = v;
    #pragma unroll
    for (int o = 16; o > 0; o >>= 1) m = fmaxf(m, __shfl_xor_sync(0xffffffffu, m, o));
    if ((tid & 31) == 0) sred[tid >> 5] = m;
    __syncthreads();
    if (tid < 8) {
        float mm = sred[tid];
        #pragma unroll
        for (int o = 4; o > 0; o >>= 1) mm = fmaxf(mm, __shfl_xor_sync(0xffu, mm, o));
        if (tid == 0) sred[0] = mm;
    }
    __syncthreads();
    float mx = sred[0];
    __syncthreads();

    float p = (tid < LL) ? expf(v - mx) : 0.f;
    float s = p;
    #pragma unroll
    for (int o = 16; o > 0; o >>= 1) s += __shfl_xor_sync(0xffffffffu, s, o);
    if ((tid & 31) == 0) sred[tid >> 5] = s;
    __syncthreads();
    if (tid < 8) {
        float ss = sred[tid];
        #pragma unroll
        for (int o = 4; o > 0; o >>= 1) ss += __shfl_xor_sync(0xffu, ss, o);
        if (tid == 0) sred[0] = ss;
    }
    __syncthreads();
    float alpha = p / sred[0];
    if (tid < LL) sAl[tid] = alpha;
    if (ec == 0 && tid < LL)
        out[ALPHA_OFF + ((size_t)b*MAXT + t)*LL + tid] = alpha;
    __syncthreads();

    int e = ec*256 + tid;
    const float* pe = enc + (size_t)g_sidx[b]*LL*ED + e;
    float acc = 0.f;
    #pragma unroll 4
    for (int l = 0; l < LL; l++) acc += sAl[l] * pe[(size_t)l*ED];
    g_xcat[(size_t)b*XK + 512 + e] = acc * g_beta[b];
}

// ------------------- gate reduce + LSTM pointwise + pack h -------------------
__global__ void k_lstm(const float* __restrict__ b_ih, const float* __restrict__ b_hh, int t)
{
    int b = blockIdx.x;
    if (b >= g_nb[t]) return;
    int tid = threadIdx.x;
    float hv[2];
    #pragma unroll
    for (int jj = 0; jj < 2; jj++) {
        int j = 2*tid + jj;
        float gi = b_ih[j]        + b_hh[j];
        float gf = b_ih[512 + j]  + b_hh[512 + j];
        float gg = b_ih[1024 + j] + b_hh[1024 + j];
        float go = b_ih[1536 + j] + b_hh[1536 + j];
        #pragma unroll
        for (int ks = 0; ks < GSPLIT; ks++) {
            const float* gp = g_gatesPart + ((size_t)ks*Bb + b)*2048;
            gi += gp[j]; gf += gp[512 + j]; gg += gp[1024 + j]; go += gp[1536 + j];
        }
        float i_ = sigmoidf_(gi);
        float f_ = sigmoidf_(gf);
        float g2 = tanhf(gg);
        float o_ = sigmoidf_(go);
        float c = f_ * g_c[b*DD + j] + i_ * g2;
        float h = o_ * tanhf(c);
        g_c[b*DD + j] = c;
        g_h[b*DD + j] = h;
        hv[jj] = h;
    }
    g_hPk[b*(DD/2) + tid] = packsplit(hv[0], hv[1]);
}

// ------------------- fc partial reduce + bias + masked store -------------------
__global__ void k_fcred(const float* __restrict__ fc_b, float* __restrict__ out, int t)
{
    int b = blockIdx.y;
    if (b >= g_nb[t]) return;
    int n = blockIdx.x*256 + threadIdx.x;
    if (n >= VV) return;
    float v = g_fcPart[(size_t)b*FCLD + n]
            + g_fcPart[(size_t)(Bb + b)*FCLD + n]
            + fc_b[n];
    out[PRED_OFF + (size_t)b*MAXT*VV + (size_t)t*VV + n] = v;
}

// ------------------- host -------------------
extern "C" void kernel_launch(void* const* d_in, const int* in_sizes, int n_in,
                              void* d_out_v, int out_size)
{
    const float* enc   = (const float*)d_in[0];
    const int*   caps  = (const int*)  d_in[1];
    const int*   lens  = (const int*)  d_in[2];
    const float* embT  = (const float*)d_in[3];
    const float* W_a   = (const float*)d_in[4];
    const float* U_a   = (const float*)d_in[5];
    const float* w_att = (const float*)d_in[6];
    const float* fb_W  = (const float*)d_in[7];
    const float* fb_b  = (const float*)d_in[8];
    const float* W_ih  = (const float*)d_in[9];
    const float* W_hh  = (const float*)d_in[10];
    const float* b_ih  = (const float*)d_in[11];
    const float* b_hh  = (const float*)d_in[12];
    const float* fc_W  = (const float*)d_in[13];
    const float* fc_b  = (const float*)d_in[14];
    const float* ih_W  = (const float*)d_in[15];
    const float* ih_b  = (const float*)d_in[16];
    const float* ic_W  = (const float*)d_in[17];
    const float* ic_b  = (const float*)d_in[18];
    float* out = (float*)d_out_v;

    void *pEncPk, *pWaT, *pUaT, *pWcat, *pFcT, *pIhT, *pIcT, *pMeanPk, *pXcatPk, *pHPk;
    void *pWaEnc, *pHU, *pGates, *pFc, *pInit;
    cudaGetSymbolAddress(&pEncPk,  g_encPk);
    cudaGetSymbolAddress(&pWaT,    g_WaT);
    cudaGetSymbolAddress(&pUaT,    g_UaT);
    cudaGetSymbolAddress(&pWcat,   g_WcatPk);
    cudaGetSymbolAddress(&pFcT,    g_fcT);
    cudaGetSymbolAddress(&pIhT,    g_ihT);
    cudaGetSymbolAddress(&pIcT,    g_icT);
    cudaGetSymbolAddress(&pMeanPk, g_meanPk);
    cudaGetSymbolAddress(&pXcatPk, g_xcatPk);
    cudaGetSymbolAddress(&pHPk,    g_hPk);
    cudaGetSymbolAddress(&pWaEnc,  g_WaEnc);
    cudaGetSymbolAddress(&pHU,     g_hUpart);
    cudaGetSymbolAddress(&pGates,  g_gatesPart);
    cudaGetSymbolAddress(&pFc,     g_fcPart);
    cudaGetSymbolAddress(&pInit,   g_initPart);

    cudaMemsetAsync(out, 0, (size_t)out_size * sizeof(float), 0);

    k_sort<<<1, 64>>>(lens, caps, out);
    k_cvt_enc<<<Bb*LL, 256>>>(enc);
    k_cvt_wcat<<<2048, 256>>>(W_ih, W_hh);
    k_cvt_wT<<<dim3(ED/2, 2), 256>>>(W_a,  (uint2*)pWaT, AD, AD, ED/2);     // [512][1024]
    k_cvt_wT<<<dim3(DD/2, 2), 256>>>(U_a,  (uint2*)pUaT, AD, AD, DD/2);     // [512][256]
    k_cvt_wT<<<dim3(DD/2, 40), 256>>>(fc_W, (uint2*)pFcT, VV, FCN, DD/2);   // [10112][256]
    k_cvt_wT<<<dim3(ED/2, 2), 256>>>(ih_W, (uint2*)pIhT, DD, DD, ED/2);
    k_cvt_wT<<<dim3(ED/2, 2), 256>>>(ic_W, (uint2*)pIcT, DD, DD, ED/2);
    k_mean<<<dim3(Bb, 4), 256>>>(enc);

    // h0/c0 partials: M=64, N=512, K=2048, z=8
    wgemm<false><<<dim3(4, 1, 8), 256>>>(
        (const uint2*)pMeanPk, (const uint2*)pIhT, (float*)pInit, 64, ED/2, ED/2, ED/2, 512);
    wgemm<false><<<dim3(4, 1, 8), 256>>>(
        (const uint2*)pMeanPk, (const uint2*)pIcT,
        (float*)pInit + (size_t)8*Bb*DD, 64, ED/2, ED/2, ED/2, 512);
    k_init<<<Bb, 256>>>(ih_b, ic_b);

    // WaEnc = enc[sidx] @ W_a : M=12544, N=512, K=2048, z=1, direct store
    wgemm<true><<<dim3(4, 196, 1), 256>>>(
        (const uint2*)pEncPk, (const uint2*)pWaT, (float*)pWaEnc, 12544, ED/2, ED/2, ED/2, 512);

    for (int t = 0; t < MAXT; t++) {
        // hU partials: M=64, N=512, K=512, z=4
        wgemm<false><<<dim3(4, 1, HSPLIT), 256>>>(
            (const uint2*)pHPk, (const uint2*)pUaT, (float*)pHU, 64, DD/2, DD/2, DD/2, 512);

        k_energy<<<dim3(Bb, 4), 256>>>(caps, embT, fb_W, fb_b, w_att, t);
        k_context<<<dim3(Bb, 8), 256>>>(enc, out, t);
        k_cvt_xcat<<<dim3(Bb, 6), 256>>>(t);

        // gates partials: M=64, N=2048, K=3072, z=12
        wgemm<false><<<dim3(16, 1, GSPLIT), 256>>>(
            (const uint2*)pXcatPk, (const uint2*)pWcat, (float*)pGates, 64, XK/2, XK/2, XK/2, 2048);

        k_lstm<<<Bb, 256>>>(b_ih, b_hh, t);

        // fc partials: M=64, N=10112(padded), K=512, z=2
        wgemm<false><<<dim3(79, 1, 2), 256>>>(
            (const uint2*)pHPk, (const uint2*)pFcT, (float*)pFc, 64, DD/2, DD/2, DD/2, FCLD);
        k_fcred<<<dim3(40, Bb), 256>>>(fc_b, out, t);
    }
}